// round 1
// baseline (speedup 1.0000x reference)
#include <cuda_runtime.h>
#include <math.h>

#define NSEQ 8192
#define DIM 512
#define HEADS 8
#define DH 64
#define FFD 2048
#define LLMD 4096

// ---------------- static scratch (no runtime allocation allowed) ----------------
__device__ float g_X[NSEQ * DIM];
__device__ float g_H[NSEQ * DIM];
__device__ float g_Q[NSEQ * DIM];
__device__ float g_K[NSEQ * DIM];
__device__ float g_V[NSEQ * DIM];
__device__ float g_O[NSEQ * DIM];
__device__ float g_G[NSEQ * FFD];
__device__ float g_pbuf[64 * DIM];
__device__ float g_colmax[DIM];
__device__ float g_colinv[DIM];
__device__ float g_ctx[HEADS * DH * DH];

// ---------------- positional encoding add ----------------
__global__ void pe_kernel(const float* __restrict__ x, float* __restrict__ X) {
    int i = blockIdx.x * 256 + threadIdx.x;      // NSEQ*DIM threads
    int n = i >> 9;                               // /512
    int d = i & 511;
    int e = d & ~1;                               // even exponent index
    float divv = expf((float)e * (-9.210340371976184f / 512.0f));
    float ang = (float)n * divv;
    float pe = (d & 1) ? cosf(ang) : sinf(ang);
    X[i] = x[i] + pe;
}

// ---------------- layernorm: one block (128 thr) per row ----------------
__global__ void ln_kernel(const float* __restrict__ X, const float* __restrict__ g,
                          const float* __restrict__ b, float* __restrict__ H) {
    int row = blockIdx.x;
    int t = threadIdx.x;  // 0..127, 4 floats each
    const float4* xr = (const float4*)(X + row * DIM);
    float4 v = xr[t];
    float s = v.x + v.y + v.z + v.w;
    float s2 = v.x * v.x + v.y * v.y + v.z * v.z + v.w * v.w;
#pragma unroll
    for (int o = 16; o; o >>= 1) {
        s  += __shfl_xor_sync(0xffffffffu, s, o);
        s2 += __shfl_xor_sync(0xffffffffu, s2, o);
    }
    __shared__ float ss[4], ss2[4];
    if ((t & 31) == 0) { ss[t >> 5] = s; ss2[t >> 5] = s2; }
    __syncthreads();
    s  = ss[0] + ss[1] + ss[2] + ss[3];
    s2 = ss2[0] + ss2[1] + ss2[2] + ss2[3];
    float mu  = s * (1.0f / DIM);
    float var = s2 * (1.0f / DIM) - mu * mu;
    float rstd = rsqrtf(var + 1e-5f);
    float4 gg = ((const float4*)g)[t];
    float4 bb = ((const float4*)b)[t];
    float4 o4;
    o4.x = (v.x - mu) * rstd * gg.x + bb.x;
    o4.y = (v.y - mu) * rstd * gg.y + bb.y;
    o4.z = (v.z - mu) * rstd * gg.z + bb.z;
    o4.w = (v.w - mu) * rstd * gg.w + bb.w;
    ((float4*)(H + row * DIM))[t] = o4;
}

// ---------------- generic SGEMM 128x128x8, 256 thr, 8x8 microtile ----------------
// EPI: 0=none, 1=+bias, 2=+bias+residual, 3=+bias then exact GELU
__device__ __forceinline__ float gelu_exact(float v) {
    return 0.5f * v * (1.0f + erff(v * 0.70710678118654752f));
}

template <int EPI>
__global__ void __launch_bounds__(256, 2)
gemm_kernel(const float* __restrict__ A, const float* __restrict__ B,
            float* __restrict__ C, const float* __restrict__ bias,
            const float* __restrict__ R, int M, int N, int K) {
    __shared__ float As[8][128];
    __shared__ float Bs[8][128];
    int tid = threadIdx.x;
    int cBase = blockIdx.x * 128;
    int rBase = blockIdx.y * 128;
    int tx = tid & 15;       // column microtile
    int ty = tid >> 4;       // row microtile
    int arow = tid >> 1, ac4 = (tid & 1) * 4;
    int brow = tid >> 5, bc4 = (tid & 31) * 4;
    const float* Aptr = A + (rBase + arow) * K + ac4;
    const float* Bptr = B + brow * N + cBase + bc4;

    float acc[8][8];
#pragma unroll
    for (int i = 0; i < 8; i++)
#pragma unroll
        for (int j = 0; j < 8; j++) acc[i][j] = 0.0f;

    for (int k0 = 0; k0 < K; k0 += 8) {
        float4 av = *(const float4*)(Aptr + k0);
        float4 bv = *(const float4*)(Bptr + k0 * N);
        As[ac4 + 0][arow] = av.x;
        As[ac4 + 1][arow] = av.y;
        As[ac4 + 2][arow] = av.z;
        As[ac4 + 3][arow] = av.w;
        *(float4*)&Bs[brow][bc4] = bv;
        __syncthreads();
#pragma unroll
        for (int kk = 0; kk < 8; kk++) {
            float4 a0 = *(float4*)&As[kk][ty * 8];
            float4 a1 = *(float4*)&As[kk][ty * 8 + 4];
            float4 b0 = *(float4*)&Bs[kk][tx * 8];
            float4 b1 = *(float4*)&Bs[kk][tx * 8 + 4];
            float ar[8] = {a0.x, a0.y, a0.z, a0.w, a1.x, a1.y, a1.z, a1.w};
            float br[8] = {b0.x, b0.y, b0.z, b0.w, b1.x, b1.y, b1.z, b1.w};
#pragma unroll
            for (int i = 0; i < 8; i++)
#pragma unroll
                for (int j = 0; j < 8; j++) acc[i][j] += ar[i] * br[j];
        }
        __syncthreads();
    }

    int col0 = cBase + tx * 8;
#pragma unroll
    for (int i = 0; i < 8; i++) {
        int row = rBase + ty * 8 + i;
        float* crow = C + (size_t)row * N + col0;
#pragma unroll
        for (int j = 0; j < 8; j++) {
            float v = acc[i][j];
            if (EPI >= 1) v += bias[col0 + j];
            if (EPI == 2) v += R[(size_t)row * N + col0 + j];
            if (EPI == 3) v = gelu_exact(v);
            crow[j] = v;
        }
    }
}

// ---------------- q softmax over feature dim (per head), * DH^-0.5 ----------------
__global__ void qsoftmax_kernel(float* __restrict__ Q) {
    int row = blockIdx.x;
    int wid = threadIdx.x >> 5;   // head
    int lane = threadIdx.x & 31;
    float2* p = (float2*)(Q + row * DIM + wid * DH) + lane;
    float2 v = *p;
    float m = fmaxf(v.x, v.y);
#pragma unroll
    for (int o = 16; o; o >>= 1) m = fmaxf(m, __shfl_xor_sync(0xffffffffu, m, o));
    float e0 = __expf(v.x - m), e1 = __expf(v.y - m);
    float s = e0 + e1;
#pragma unroll
    for (int o = 16; o; o >>= 1) s += __shfl_xor_sync(0xffffffffu, s, o);
    float inv = 0.125f / s;   // scale = DH^-0.5 = 0.125
    v.x = e0 * inv;
    v.y = e1 * inv;
    *p = v;
}

// ---------------- k column softmax (over sequence) ----------------
__global__ void kcolmax_kernel(const float* __restrict__ Kb, float* __restrict__ pmax) {
    int c = threadIdx.x;           // 512 threads = columns
    int chunk = blockIdx.x;        // 64 chunks of 128 rows
    const float* p = Kb + chunk * 128 * DIM + c;
    float m = -1e30f;
#pragma unroll 4
    for (int r = 0; r < 128; r++) m = fmaxf(m, p[r * DIM]);
    pmax[chunk * DIM + c] = m;
}

__global__ void kcolmax_reduce(const float* __restrict__ pmax, float* __restrict__ colmax) {
    int c = threadIdx.x;
    float m = -1e30f;
#pragma unroll 8
    for (int i = 0; i < 64; i++) m = fmaxf(m, pmax[i * DIM + c]);
    colmax[c] = m;
}

__global__ void kexp_kernel(float* __restrict__ Kb, const float* __restrict__ colmax,
                            float* __restrict__ psum) {
    int c = threadIdx.x;
    int chunk = blockIdx.x;
    float m = colmax[c];
    float* p = Kb + chunk * 128 * DIM + c;
    float s = 0.0f;
#pragma unroll 4
    for (int r = 0; r < 128; r++) {
        float e = __expf(p[r * DIM] - m);
        p[r * DIM] = e;
        s += e;
    }
    psum[chunk * DIM + c] = s;
}

__global__ void kcolsum_reduce(const float* __restrict__ psum, float* __restrict__ colinv) {
    int c = threadIdx.x;
    float s = 0.0f;
#pragma unroll 8
    for (int i = 0; i < 64; i++) s += psum[i * DIM + c];
    colinv[c] = 1.0f / s;
}

// ---------------- ctx = E^T V per head (block-diagonal 64x64), chunked + atomics ----------------
__global__ void ctx_zero_kernel(float* __restrict__ ctx) {
    ctx[blockIdx.x * 256 + threadIdx.x] = 0.0f;
}

__global__ void __launch_bounds__(256)
ctx_kernel(const float* __restrict__ E, const float* __restrict__ V, float* __restrict__ ctx) {
    int h = blockIdx.x;       // head
    int chunk = blockIdx.y;   // 16 chunks of 512 rows
    __shared__ float Es[32][64];
    __shared__ float Vs[32][64];
    int tid = threadIdx.x;
    int tx = tid & 15, ty = tid >> 4;
    float acc[4][4] = {};
    int rbase = chunk * 512;
    for (int r0 = 0; r0 < 512; r0 += 32) {
#pragma unroll
        for (int ld = 0; ld < 2; ld++) {
            int ii = tid + ld * 256;           // 512 float4 loads
            int rr = ii >> 4, c4 = (ii & 15) * 4;
            const float* eb = E + (rbase + r0 + rr) * DIM + h * DH + c4;
            const float* vb = V + (rbase + r0 + rr) * DIM + h * DH + c4;
            *(float4*)&Es[rr][c4] = *(const float4*)eb;
            *(float4*)&Vs[rr][c4] = *(const float4*)vb;
        }
        __syncthreads();
#pragma unroll
        for (int r = 0; r < 32; r++) {
            float4 a4 = *(float4*)&Es[r][ty * 4];
            float4 b4 = *(float4*)&Vs[r][tx * 4];
            float a[4] = {a4.x, a4.y, a4.z, a4.w};
            float b[4] = {b4.x, b4.y, b4.z, b4.w};
#pragma unroll
            for (int i = 0; i < 4; i++)
#pragma unroll
                for (int j = 0; j < 4; j++) acc[i][j] += a[i] * b[j];
        }
        __syncthreads();
    }
#pragma unroll
    for (int i = 0; i < 4; i++)
#pragma unroll
        for (int j = 0; j < 4; j++)
            atomicAdd(&ctx[h * (DH * DH) + (ty * 4 + i) * DH + tx * 4 + j], acc[i][j]);
}

__global__ void ctx_fix_kernel(float* __restrict__ ctx, const float* __restrict__ colinv) {
    int i = blockIdx.x * 256 + threadIdx.x;    // 8*64*64 = 32768
    int h = i >> 12;
    int d = (i >> 6) & 63;
    ctx[i] *= colinv[h * DH + d];
}

// ---------------- o = q_sm @ ctx per head ----------------
__global__ void __launch_bounds__(256)
attn_o_kernel(const float* __restrict__ Q, const float* __restrict__ ctx,
              float* __restrict__ O) {
    int nt = blockIdx.x;   // 128 tiles of 64 rows
    int h = blockIdx.y;
    __shared__ float Cs[64][64];
    __shared__ float Qs[64][64];
    int tid = threadIdx.x;
#pragma unroll
    for (int ld = 0; ld < 4; ld++) {
        int ii = tid + ld * 256;              // 1024 float4 loads per matrix
        int rr = ii >> 4, c4 = (ii & 15) * 4;
        *(float4*)&Cs[rr][c4] = *(const float4*)(ctx + h * (DH * DH) + rr * DH + c4);
        *(float4*)&Qs[rr][c4] = *(const float4*)(Q + (nt * 64 + rr) * DIM + h * DH + c4);
    }
    __syncthreads();
    int tx = tid & 15, ty = tid >> 4;
    float acc[4][4] = {};
#pragma unroll 8
    for (int d = 0; d < 64; d++) {
        float a[4];
#pragma unroll
        for (int i = 0; i < 4; i++) a[i] = Qs[ty * 4 + i][d];  // 2-way broadcast within warp
        float4 b4 = *(float4*)&Cs[d][tx * 4];
        float b[4] = {b4.x, b4.y, b4.z, b4.w};
#pragma unroll
        for (int i = 0; i < 4; i++)
#pragma unroll
            for (int j = 0; j < 4; j++) acc[i][j] += a[i] * b[j];
    }
#pragma unroll
    for (int i = 0; i < 4; i++) {
        float4 o4 = make_float4(acc[i][0], acc[i][1], acc[i][2], acc[i][3]);
        *(float4*)(O + (nt * 64 + ty * 4 + i) * DIM + h * DH + tx * 4) = o4;
    }
}

// ---------------- host orchestration ----------------
extern "C" void kernel_launch(void* const* d_in, const int* in_sizes, int n_in,
                              void* d_out, int out_size) {
    const float* x      = (const float*)d_in[0];
    const float* ln1_g  = (const float*)d_in[1];
    const float* ln1_b  = (const float*)d_in[2];
    const float* Wq     = (const float*)d_in[3];
    const float* Wk     = (const float*)d_in[4];
    const float* Wv     = (const float*)d_in[5];
    const float* Wo     = (const float*)d_in[6];
    const float* bo     = (const float*)d_in[7];
    const float* ln2_g  = (const float*)d_in[8];
    const float* ln2_b  = (const float*)d_in[9];
    const float* W1     = (const float*)d_in[10];
    const float* b1     = (const float*)d_in[11];
    const float* W2     = (const float*)d_in[12];
    const float* b2     = (const float*)d_in[13];
    const float* projW  = (const float*)d_in[14];
    const float* projb  = (const float*)d_in[15];
    float* out = (float*)d_out;

    float *X, *H, *Q, *K, *V, *O, *G, *pbuf, *colmax, *colinv, *ctx;
    cudaGetSymbolAddress((void**)&X, g_X);
    cudaGetSymbolAddress((void**)&H, g_H);
    cudaGetSymbolAddress((void**)&Q, g_Q);
    cudaGetSymbolAddress((void**)&K, g_K);
    cudaGetSymbolAddress((void**)&V, g_V);
    cudaGetSymbolAddress((void**)&O, g_O);
    cudaGetSymbolAddress((void**)&G, g_G);
    cudaGetSymbolAddress((void**)&pbuf, g_pbuf);
    cudaGetSymbolAddress((void**)&colmax, g_colmax);
    cudaGetSymbolAddress((void**)&colinv, g_colinv);
    cudaGetSymbolAddress((void**)&ctx, g_ctx);

    pe_kernel<<<NSEQ * DIM / 256, 256>>>(x, X);

    dim3 gDD(DIM / 128, NSEQ / 128);     // M x 512 GEMMs
    dim3 gFF(FFD / 128, NSEQ / 128);     // M x 2048
    dim3 gLL(LLMD / 128, NSEQ / 128);    // M x 4096
    dim3 gctx(HEADS, 16);
    dim3 go(NSEQ / 64, HEADS);

    for (int l = 0; l < 2; l++) {
        const float* wq = Wq + l * DIM * DIM;
        const float* wk = Wk + l * DIM * DIM;
        const float* wv = Wv + l * DIM * DIM;
        const float* wo = Wo + l * DIM * DIM;
        const float* w1 = W1 + l * DIM * FFD;
        const float* w2 = W2 + l * FFD * DIM;

        ln_kernel<<<NSEQ, 128>>>(X, ln1_g + l * DIM, ln1_b + l * DIM, H);
        gemm_kernel<0><<<gDD, 256>>>(H, wq, Q, nullptr, nullptr, NSEQ, DIM, DIM);
        gemm_kernel<0><<<gDD, 256>>>(H, wk, K, nullptr, nullptr, NSEQ, DIM, DIM);
        gemm_kernel<0><<<gDD, 256>>>(H, wv, V, nullptr, nullptr, NSEQ, DIM, DIM);

        qsoftmax_kernel<<<NSEQ, 256>>>(Q);

        kcolmax_kernel<<<64, 512>>>(K, pbuf);
        kcolmax_reduce<<<1, 512>>>(pbuf, colmax);
        kexp_kernel<<<64, 512>>>(K, colmax, pbuf);
        kcolsum_reduce<<<1, 512>>>(pbuf, colinv);

        ctx_zero_kernel<<<HEADS * DH * DH / 256, 256>>>(ctx);
        ctx_kernel<<<gctx, 256>>>(K, V, ctx);
        ctx_fix_kernel<<<HEADS * DH * DH / 256, 256>>>(ctx, colinv);

        attn_o_kernel<<<go, 256>>>(Q, ctx, O);

        gemm_kernel<2><<<gDD, 256>>>(O, wo, X, bo + l * DIM, X, NSEQ, DIM, DIM);

        ln_kernel<<<NSEQ, 128>>>(X, ln2_g + l * DIM, ln2_b + l * DIM, H);
        gemm_kernel<3><<<gFF, 256>>>(H, w1, G, b1 + l * FFD, nullptr, NSEQ, FFD, DIM);
        gemm_kernel<2><<<gDD, 256>>>(G, w2, X, b2 + l * DIM, X, NSEQ, DIM, FFD);
    }

    gemm_kernel<1><<<gLL, 256>>>(X, projW, out, projb, nullptr, NSEQ, LLMD, DIM);
}